// round 6
// baseline (speedup 1.0000x reference)
#include <cuda_runtime.h>
#include <cuda_bf16.h>
#include <math.h>

#define BATCH 2
#define TT    2048
#define TOK   (BATCH * TT)      // 4096
#define DD    1024
#define HH    16
#define HDIM  64
#define INNER (HH * HDIM)       // 1024
#define VOCAB 32000
#define FFN   (4 * DD)          // 4096

typedef __nv_bfloat16 bf16;

// ---------------- scratch ----------------
__device__ float g_h  [TOK * DD];
__device__ float g_qkv[TOK * 3 * INNER];

__device__ __align__(128) bf16 g_h1_hi[TOK * DD],   g_h1_lo[TOK * DD];
__device__ __align__(128) bf16 g_att_hi[TOK * INNER], g_att_lo[TOK * INNER];
__device__ __align__(128) bf16 g_ff1_hi[TOK * FFN], g_ff1_lo[TOK * FFN];
__device__ __align__(128) bf16 g_hs_hi[TOK * DD],   g_hs_lo[TOK * DD];

__device__ __align__(128) bf16 g_wqkv_hi[DD * 3 * INNER], g_wqkv_lo[DD * 3 * INNER];
__device__ __align__(128) bf16 g_wout_hi[INNER * DD],     g_wout_lo[INNER * DD];
__device__ __align__(128) bf16 g_wf1_hi[DD * FFN],        g_wf1_lo[DD * FFN];
__device__ __align__(128) bf16 g_wf2_hi[FFN * DD],        g_wf2_lo[FFN * DD];
__device__ __align__(128) bf16 g_wh_hi[DD * VOCAB],       g_wh_lo[DD * VOCAB];

// ---------------- helpers ----------------
__device__ __forceinline__ unsigned smem_addr_u32(const void* p) {
    return (unsigned)__cvta_generic_to_shared(p);
}
__device__ __forceinline__ unsigned pack_bf16x2(bf16 a, bf16 b) {
    __nv_bfloat162 p = __halves2bfloat162(a, b);
    return *(unsigned*)&p;
}
__device__ __forceinline__ void split2(float v0, float v1, unsigned& hi, unsigned& lo) {
    bf16 h0 = __float2bfloat16(v0);
    bf16 h1 = __float2bfloat16(v1);
    bf16 l0 = __float2bfloat16(v0 - __bfloat162float(h0));
    bf16 l1 = __float2bfloat16(v1 - __bfloat162float(h1));
    hi = pack_bf16x2(h0, h1);
    lo = pack_bf16x2(l0, l1);
}

__device__ __forceinline__ float block_sum256(float v) {
    __shared__ float red[8];
    const unsigned FULL = 0xffffffffu;
    #pragma unroll
    for (int o = 16; o > 0; o >>= 1) v += __shfl_down_sync(FULL, v, o);
    __syncthreads();
    if ((threadIdx.x & 31) == 0) red[threadIdx.x >> 5] = v;
    __syncthreads();
    float s = 0.f;
    #pragma unroll
    for (int i = 0; i < 8; i++) s += red[i];
    return s;
}

__device__ __forceinline__ int fetch_token(const void* xraw, int t) {
    const int* x32 = (const int*)xraw;
    bool is64 = true;
    #pragma unroll
    for (int i = 0; i < 8; i++) if (x32[2 * i + 1] != 0) is64 = false;
    return is64 ? (int)(((const long long*)xraw)[t]) : x32[t];
}

// ---------------- weight split: fp32 -> bf16 hi/lo ----------------
__global__ void split_kernel(const float4* __restrict__ s,
                             uint2* __restrict__ hi, uint2* __restrict__ lo, int n4) {
    int i = blockIdx.x * blockDim.x + threadIdx.x;
    int stride = gridDim.x * blockDim.x;
    for (; i < n4; i += stride) {
        float4 v = s[i];
        unsigned h01, l01, h23, l23;
        split2(v.x, v.y, h01, l01);
        split2(v.z, v.w, h23, l23);
        hi[i] = make_uint2(h01, h23);
        lo[i] = make_uint2(l01, l23);
    }
}

// ---------------- embed + pos + LN1 (h fp32, h1 split) ----------------
__global__ void embed_ln_kernel(const void* __restrict__ x,
                                const float* __restrict__ emb,
                                const float* __restrict__ pos,
                                const float* __restrict__ g,
                                const float* __restrict__ b,
                                float* __restrict__ h,
                                bf16* __restrict__ o_hi, bf16* __restrict__ o_lo) {
    const int t    = blockIdx.x;
    const int tpos = t & (TT - 1);
    const int tok = fetch_token(x, t);
    const float* e = emb + (size_t)tok * DD;
    const float* p = pos + (size_t)tpos * DD;

    float local[4];
    float s = 0.f;
    #pragma unroll
    for (int i = 0; i < 4; i++) {
        int idx = threadIdx.x + i * 256;
        float v = e[idx] + p[idx];
        local[i] = v;
        h[(size_t)t * DD + idx] = v;
        s += v;
    }
    float S = block_sum256(s);
    float mu = S * (1.0f / DD);
    float s2 = 0.f;
    #pragma unroll
    for (int i = 0; i < 4; i++) { float d = local[i] - mu; s2 += d * d; }
    float V = block_sum256(s2);
    float rstd = rsqrtf(V * (1.0f / DD) + 1e-5f);
    #pragma unroll
    for (int i = 0; i < 4; i++) {
        int idx = threadIdx.x + i * 256;
        float v = (local[i] - mu) * rstd * g[idx] + b[idx];
        bf16 hv = __float2bfloat16(v);
        o_hi[(size_t)t * DD + idx] = hv;
        o_lo[(size_t)t * DD + idx] = __float2bfloat16(v - __bfloat162float(hv));
    }
}

// ---------------- LN2 (reads fp32 h, writes split) ----------------
__global__ void ln_kernel(const float* __restrict__ h,
                          const float* __restrict__ g,
                          const float* __restrict__ b,
                          bf16* __restrict__ o_hi, bf16* __restrict__ o_lo) {
    const int t = blockIdx.x;
    float local[4];
    float s = 0.f;
    #pragma unroll
    for (int i = 0; i < 4; i++) {
        int idx = threadIdx.x + i * 256;
        float v = h[(size_t)t * DD + idx];
        local[i] = v;
        s += v;
    }
    float S = block_sum256(s);
    float mu = S * (1.0f / DD);
    float s2 = 0.f;
    #pragma unroll
    for (int i = 0; i < 4; i++) { float d = local[i] - mu; s2 += d * d; }
    float V = block_sum256(s2);
    float rstd = rsqrtf(V * (1.0f / DD) + 1e-5f);
    #pragma unroll
    for (int i = 0; i < 4; i++) {
        int idx = threadIdx.x + i * 256;
        float v = (local[i] - mu) * rstd * g[idx] + b[idx];
        bf16 hv = __float2bfloat16(v);
        o_hi[(size_t)t * DD + idx] = hv;
        o_lo[(size_t)t * DD + idx] = __float2bfloat16(v - __bfloat162float(hv));
    }
}

// ================= tensor-core GEMM v2: pre-split bf16x3, cp.async 2-stage =================
// D(MxN) = A(MxK)@B(KxN) with A=Ah+Al, B=Bh+Bl (3 passes, drop Al*Bl)
// CTA 128x128, BK=32, 256 thr, 8 warps (4M x 2N), warp tile 32x64.
// SMEM (dynamic, 75776B): A stage/part 128x40 bf16, B stage/part 32x136 bf16.

#define LDA_S 40
#define LDB_S 136
#define A_PART_SZ (128 * LDA_S)   // 5120
#define B_PART_SZ (32 * LDB_S)    // 4352
#define SMEM_BYTES ((4 * A_PART_SZ + 4 * B_PART_SZ) * 2)

__device__ __forceinline__ void ldmatrix_x4(unsigned* r, unsigned addr) {
    asm volatile("ldmatrix.sync.aligned.m8n8.x4.shared.b16 {%0,%1,%2,%3}, [%4];"
                 : "=r"(r[0]), "=r"(r[1]), "=r"(r[2]), "=r"(r[3]) : "r"(addr));
}
__device__ __forceinline__ void ldmatrix_x4_trans(unsigned* r, unsigned addr) {
    asm volatile("ldmatrix.sync.aligned.m8n8.x4.trans.shared.b16 {%0,%1,%2,%3}, [%4];"
                 : "=r"(r[0]), "=r"(r[1]), "=r"(r[2]), "=r"(r[3]) : "r"(addr));
}
__device__ __forceinline__ void mma_bf16(float* c, const unsigned* a, const unsigned* b) {
    asm volatile("mma.sync.aligned.m16n8k16.row.col.f32.bf16.bf16.f32 "
                 "{%0,%1,%2,%3}, {%4,%5,%6,%7}, {%8,%9}, {%0,%1,%2,%3};"
                 : "+f"(c[0]), "+f"(c[1]), "+f"(c[2]), "+f"(c[3])
                 : "r"(a[0]), "r"(a[1]), "r"(a[2]), "r"(a[3]), "r"(b[0]), "r"(b[1]));
}
__device__ __forceinline__ void cp16(unsigned saddr, const void* gptr) {
    asm volatile("cp.async.cg.shared.global [%0], [%1], 16;" :: "r"(saddr), "l"(gptr));
}

template<int DO_BIAS, int DO_ADDC, int DO_GELU, int DO_SPLIT, int DO_F32>
__global__ __launch_bounds__(256)
void gemm_bf3(int M, int N, int K,
              const bf16* __restrict__ Ah, const bf16* __restrict__ Al,
              const bf16* __restrict__ Bh, const bf16* __restrict__ Bl,
              const float* __restrict__ Cadd, const float* __restrict__ bias,
              float* __restrict__ D,
              bf16* __restrict__ Dh, bf16* __restrict__ Dl) {
    extern __shared__ __align__(16) bf16 dynsm[];
    bf16* SA = dynsm;                       // [4][A_PART_SZ]  (stage*2+part)
    bf16* SB = dynsm + 4 * A_PART_SZ;       // [4][B_PART_SZ]

    const int tid  = threadIdx.x;
    const int lane = tid & 31;
    const int warp = tid >> 5;
    const int wm   = warp & 3;
    const int wn   = warp >> 2;
    const int bx = blockIdx.x;
    const int by = blockIdx.y;

    float acc[2][8][4];
    #pragma unroll
    for (int i = 0; i < 2; i++)
        #pragma unroll
        for (int j = 0; j < 8; j++)
            #pragma unroll
            for (int q = 0; q < 4; q++) acc[i][j][q] = 0.f;

    const int a_row = wm * 32 + (lane & 15);
    const int a_col = (lane >> 4) * 8;
    const int b_row = (lane & 15);
    const int b_col = wn * 64 + (lane >> 4) * 8;

    // cp.async tile loaders
    const int a_r = tid >> 2;            // A: thread -> (row, 16B chunk)
    const int a_c = (tid & 3) * 8;
    const int b_r = tid >> 4;            // B: thread -> (row, 16B chunk)
    const int b_c = (tid & 15) * 8;

    const size_t a_goff0 = (size_t)(by * 128 + a_r) * K + a_c;
    const size_t a_goff1 = (size_t)(by * 128 + a_r + 64) * K + a_c;
    const size_t b_goff0 = (size_t)b_r * N + bx * 128 + b_c;
    const size_t b_goff1 = (size_t)(b_r + 16) * N + bx * 128 + b_c;

    const unsigned sa0 = smem_addr_u32(&SA[a_r * LDA_S + a_c]);
    const unsigned sa1 = smem_addr_u32(&SA[(a_r + 64) * LDA_S + a_c]);
    const unsigned sb0 = smem_addr_u32(&SB[b_r * LDB_S + b_c]);
    const unsigned sb1 = smem_addr_u32(&SB[(b_r + 16) * LDB_S + b_c]);

    const int KT = K >> 5;

    auto load_stage = [&](int st, int k0) {
        const unsigned aoff_hi = (st * 2 + 0) * A_PART_SZ * 2;   // byte offsets
        const unsigned aoff_lo = (st * 2 + 1) * A_PART_SZ * 2;
        const unsigned boff_hi = (st * 2 + 0) * B_PART_SZ * 2;
        const unsigned boff_lo = (st * 2 + 1) * B_PART_SZ * 2;
        cp16(sa0 + aoff_hi, Ah + a_goff0 + k0);
        cp16(sa1 + aoff_hi, Ah + a_goff1 + k0);
        cp16(sa0 + aoff_lo, Al + a_goff0 + k0);
        cp16(sa1 + aoff_lo, Al + a_goff1 + k0);
        cp16(sb0 + boff_hi, Bh + b_goff0 + (size_t)k0 * N);
        cp16(sb1 + boff_hi, Bh + b_goff1 + (size_t)k0 * N);
        cp16(sb0 + boff_lo, Bl + b_goff0 + (size_t)k0 * N);
        cp16(sb1 + boff_lo, Bl + b_goff1 + (size_t)k0 * N);
    };

    load_stage(0, 0);
    asm volatile("cp.async.commit_group;");

    for (int kt = 0; kt < KT; kt++) {
        if (kt + 1 < KT) {
            load_stage((kt + 1) & 1, (kt + 1) << 5);
            asm volatile("cp.async.commit_group;");
            asm volatile("cp.async.wait_group 1;");
        } else {
            asm volatile("cp.async.wait_group 0;");
        }
        __syncthreads();

        const int st = kt & 1;
        const bf16* Ash = SA + (st * 2 + 0) * A_PART_SZ;
        const bf16* Asl = SA + (st * 2 + 1) * A_PART_SZ;
        const bf16* Bsh = SB + (st * 2 + 0) * B_PART_SZ;
        const bf16* Bsl = SB + (st * 2 + 1) * B_PART_SZ;

        #pragma unroll
        for (int ks = 0; ks < 2; ks++) {
            unsigned ahf[2][4], alf[2][4], bf[16];
            #pragma unroll
            for (int mt = 0; mt < 2; mt++)
                ldmatrix_x4(ahf[mt], smem_addr_u32(&Ash[(a_row + mt * 16) * LDA_S + ks * 16 + a_col]));
            #pragma unroll
            for (int ntp = 0; ntp < 4; ntp++)
                ldmatrix_x4_trans(&bf[ntp * 4], smem_addr_u32(&Bsh[(ks * 16 + b_row) * LDB_S + b_col + ntp * 16]));
            #pragma unroll
            for (int mt = 0; mt < 2; mt++)
                #pragma unroll
                for (int nt = 0; nt < 8; nt++)
                    mma_bf16(acc[mt][nt], ahf[mt], &bf[nt * 2]);

            #pragma unroll
            for (int mt = 0; mt < 2; mt++)
                ldmatrix_x4(alf[mt], smem_addr_u32(&Asl[(a_row + mt * 16) * LDA_S + ks * 16 + a_col]));
            #pragma unroll
            for (int mt = 0; mt < 2; mt++)
                #pragma unroll
                for (int nt = 0; nt < 8; nt++)
                    mma_bf16(acc[mt][nt], alf[mt], &bf[nt * 2]);

            #pragma unroll
            for (int ntp = 0; ntp < 4; ntp++)
                ldmatrix_x4_trans(&bf[ntp * 4], smem_addr_u32(&Bsl[(ks * 16 + b_row) * LDB_S + b_col + ntp * 16]));
            #pragma unroll
            for (int mt = 0; mt < 2; mt++)
                #pragma unroll
                for (int nt = 0; nt < 8; nt++)
                    mma_bf16(acc[mt][nt], ahf[mt], &bf[nt * 2]);
        }
        __syncthreads();
    }

    // ---- epilogue ----
    const int row_base = by * 128 + wm * 32 + (lane >> 2);
    const int col_base = bx * 128 + wn * 64 + (lane & 3) * 2;
    #pragma unroll
    for (int mt = 0; mt < 2; mt++) {
        #pragma unroll
        for (int nt = 0; nt < 8; nt++) {
            int col = col_base + nt * 8;
            float2 vb;
            if (DO_BIAS) vb = *(const float2*)&bias[col];
            #pragma unroll
            for (int half = 0; half < 2; half++) {
                int row = row_base + mt * 16 + half * 8;
                float v0 = acc[mt][nt][half * 2 + 0];
                float v1 = acc[mt][nt][half * 2 + 1];
                if (DO_BIAS) { v0 += vb.x; v1 += vb.y; }
                if (DO_GELU) { v0 = v0 * normcdff(v0); v1 = v1 * normcdff(v1); }
                size_t off = (size_t)row * N + col;
                if (DO_ADDC) {
                    float2 c = *(const float2*)&Cadd[off];
                    v0 += c.x; v1 += c.y;
                }
                if (DO_F32) {
                    float2 o; o.x = v0; o.y = v1;
                    *(float2*)&D[off] = o;
                }
                if (DO_SPLIT) {
                    unsigned hp, lp;
                    split2(v0, v1, hp, lp);
                    *(unsigned*)&Dh[off] = hp;
                    *(unsigned*)&Dl[off] = lp;
                }
            }
        }
    }
}

// ---------------- flash attention (fp32 in, split out) ----------------
__global__ __launch_bounds__(64)
void flash_attn_kernel(const float* __restrict__ qkv,
                       bf16* __restrict__ o_hi, bf16* __restrict__ o_lo) {
    const int tid = threadIdx.x;
    const int qt = blockIdx.x;
    const int hh = blockIdx.y;
    const int b  = blockIdx.z;

    __shared__ float k_sm[64 * 64];
    __shared__ float v_sm[64 * 64];

    const int q_row = qt * 64 + tid;
    const float* qp = qkv + ((size_t)(b * TT + q_row)) * (3 * INNER) + hh * HDIM;

    float q[64], acc[64];
    #pragma unroll
    for (int d = 0; d < 64; d++) { q[d] = qp[d] * 0.125f; acc[d] = 0.f; }
    float m = -3.0e38f, l = 0.f;

    for (int kt = 0; kt <= qt; kt++) {
        const float* kb = qkv + ((size_t)(b * TT + kt * 64)) * (3 * INNER) + INNER + hh * HDIM;
        const float* vb = kb + INNER;
        __syncthreads();
        for (int r = 0; r < 64; r++) {
            k_sm[r * 64 + tid] = kb[(size_t)r * (3 * INNER) + tid];
            v_sm[r * 64 + tid] = vb[(size_t)r * (3 * INNER) + tid];
        }
        __syncthreads();

        const int valid = q_row - kt * 64;
        #pragma unroll
        for (int c = 0; c < 2; c++) {
            float s[32];
            float mt = -3.0e38f;
            for (int j = 0; j < 32; j++) {
                const int jj = c * 32 + j;
                float sv;
                if (jj <= valid) {
                    sv = 0.f;
                    #pragma unroll
                    for (int d = 0; d < 64; d++) sv += q[d] * k_sm[jj * 64 + d];
                } else {
                    sv = -3.0e38f;
                }
                s[j] = sv;
                mt = fmaxf(mt, sv);
            }
            if (mt > m) {
                float corr = expf(m - mt);
                l *= corr;
                #pragma unroll
                for (int d = 0; d < 64; d++) acc[d] *= corr;
                m = mt;
            }
            for (int j = 0; j < 32; j++) {
                float p = expf(s[j] - m);
                l += p;
                const int jj = c * 32 + j;
                #pragma unroll
                for (int d = 0; d < 64; d++) acc[d] += p * v_sm[jj * 64 + d];
            }
        }
    }

    const float inv = 1.0f / l;
    size_t base = ((size_t)(b * TT + q_row)) * INNER + hh * HDIM;
    #pragma unroll
    for (int d = 0; d < 64; d++) {
        float v = acc[d] * inv;
        bf16 hv = __float2bfloat16(v);
        o_hi[base + d] = hv;
        o_lo[base + d] = __float2bfloat16(v - __bfloat162float(hv));
    }
}

// ---------------- launch ----------------
extern "C" void kernel_launch(void* const* d_in, const int* in_sizes, int n_in,
                              void* d_out, int out_size) {
    const void*  x      = d_in[0];
    const float* emb    = (const float*)d_in[1];
    const float* pos    = (const float*)d_in[2];
    const float* w_qkv  = (const float*)d_in[3];
    const float* w_out  = (const float*)d_in[4];
    const float* ln1_g  = (const float*)d_in[5];
    const float* ln1_b  = (const float*)d_in[6];
    const float* ln2_g  = (const float*)d_in[7];
    const float* ln2_b  = (const float*)d_in[8];
    const float* w_ffn1 = (const float*)d_in[9];
    const float* b_ffn1 = (const float*)d_in[10];
    const float* w_ffn2 = (const float*)d_in[11];
    const float* b_ffn2 = (const float*)d_in[12];
    const float* w_head = (const float*)d_in[13];
    const float* b_head = (const float*)d_in[14];
    float* out = (float*)d_out;

    float *h, *qkv;
    bf16 *h1h, *h1l, *atth, *attl, *ff1h, *ff1l, *hsh, *hsl;
    bf16 *wqh, *wql, *woh, *wol, *w1h, *w1l, *w2h, *w2l, *whh, *whl;
    cudaGetSymbolAddress((void**)&h,    g_h);
    cudaGetSymbolAddress((void**)&qkv,  g_qkv);
    cudaGetSymbolAddress((void**)&h1h,  g_h1_hi);  cudaGetSymbolAddress((void**)&h1l,  g_h1_lo);
    cudaGetSymbolAddress((void**)&atth, g_att_hi); cudaGetSymbolAddress((void**)&attl, g_att_lo);
    cudaGetSymbolAddress((void**)&ff1h, g_ff1_hi); cudaGetSymbolAddress((void**)&ff1l, g_ff1_lo);
    cudaGetSymbolAddress((void**)&hsh,  g_hs_hi);  cudaGetSymbolAddress((void**)&hsl,  g_hs_lo);
    cudaGetSymbolAddress((void**)&wqh,  g_wqkv_hi); cudaGetSymbolAddress((void**)&wql, g_wqkv_lo);
    cudaGetSymbolAddress((void**)&woh,  g_wout_hi); cudaGetSymbolAddress((void**)&wol, g_wout_lo);
    cudaGetSymbolAddress((void**)&w1h,  g_wf1_hi);  cudaGetSymbolAddress((void**)&w1l, g_wf1_lo);
    cudaGetSymbolAddress((void**)&w2h,  g_wf2_hi);  cudaGetSymbolAddress((void**)&w2l, g_wf2_lo);
    cudaGetSymbolAddress((void**)&whh,  g_wh_hi);   cudaGetSymbolAddress((void**)&whl, g_wh_lo);

    // raise dynamic smem limits (idempotent)
    cudaFuncSetAttribute(gemm_bf3<0,0,0,0,1>, cudaFuncAttributeMaxDynamicSharedMemorySize, SMEM_BYTES);
    cudaFuncSetAttribute(gemm_bf3<0,1,0,0,1>, cudaFuncAttributeMaxDynamicSharedMemorySize, SMEM_BYTES);
    cudaFuncSetAttribute(gemm_bf3<1,0,1,1,0>, cudaFuncAttributeMaxDynamicSharedMemorySize, SMEM_BYTES);
    cudaFuncSetAttribute(gemm_bf3<1,1,0,1,0>, cudaFuncAttributeMaxDynamicSharedMemorySize, SMEM_BYTES);
    cudaFuncSetAttribute(gemm_bf3<1,0,0,0,1>, cudaFuncAttributeMaxDynamicSharedMemorySize, SMEM_BYTES);

    // 0. split weights -> bf16 hi/lo
    split_kernel<<<2048, 256>>>((const float4*)w_qkv,  (uint2*)wqh, (uint2*)wql, DD * 3 * INNER / 4);
    split_kernel<<<2048, 256>>>((const float4*)w_out,  (uint2*)woh, (uint2*)wol, INNER * DD / 4);
    split_kernel<<<2048, 256>>>((const float4*)w_ffn1, (uint2*)w1h, (uint2*)w1l, DD * FFN / 4);
    split_kernel<<<2048, 256>>>((const float4*)w_ffn2, (uint2*)w2h, (uint2*)w2l, FFN * DD / 4);
    split_kernel<<<4096, 256>>>((const float4*)w_head, (uint2*)whh, (uint2*)whl, DD * VOCAB / 4);

    // 1. embed + pos + ln1 -> h fp32, h1 split
    embed_ln_kernel<<<TOK, 256>>>(x, emb, pos, ln1_g, ln1_b, h, h1h, h1l);

    // 2. qkv = h1 @ w_qkv (fp32 out)
    gemm_bf3<0,0,0,0,1><<<dim3(3 * INNER / 128, TOK / 128), 256, SMEM_BYTES>>>(
        TOK, 3 * INNER, DD, h1h, h1l, wqh, wql, nullptr, nullptr, qkv, nullptr, nullptr);

    // 3. flash attention -> att split
    flash_attn_kernel<<<dim3(TT / 64, HH, BATCH), 64>>>(qkv, atth, attl);

    // 4. h = h + att @ w_out (fp32 out, in place on h)
    gemm_bf3<0,1,0,0,1><<<dim3(DD / 128, TOK / 128), 256, SMEM_BYTES>>>(
        TOK, DD, INNER, atth, attl, woh, wol, h, nullptr, h, nullptr, nullptr);

    // 5. h2 = ln2(h) -> split
    ln_kernel<<<TOK, 256>>>(h, ln2_g, ln2_b, h1h, h1l);

    // 6. ff1 = gelu(h2 @ w_ffn1 + b1) -> split only
    gemm_bf3<1,0,1,1,0><<<dim3(FFN / 128, TOK / 128), 256, SMEM_BYTES>>>(
        TOK, FFN, DD, h1h, h1l, w1h, w1l, nullptr, b_ffn1, nullptr, ff1h, ff1l);

    // 7. h' = h + ff1 @ w_ffn2 + b2 -> split only (feeds head)
    gemm_bf3<1,1,0,1,0><<<dim3(DD / 128, TOK / 128), 256, SMEM_BYTES>>>(
        TOK, DD, FFN, ff1h, ff1l, w2h, w2l, h, b_ffn2, nullptr, hsh, hsl);

    // 8. logits = h' @ w_head + b_head (fp32 out)
    gemm_bf3<1,0,0,0,1><<<dim3(VOCAB / 128, TOK / 128), 256, SMEM_BYTES>>>(
        TOK, VOCAB, DD, hsh, hsl, whh, whl, nullptr, b_head, out, nullptr, nullptr);
}

// round 12
// speedup vs baseline: 1.0222x; 1.0222x over previous
#include <cuda_runtime.h>
#include <cuda_bf16.h>
#include <math.h>
#include <stdint.h>

#define BATCH 2
#define TT    2048
#define TOK   (BATCH * TT)      // 4096
#define DD    1024
#define HH    16
#define HDIM  64
#define INNER (HH * HDIM)       // 1024
#define VOCAB 32000
#define FFN   (4 * DD)          // 4096

typedef __nv_bfloat16 bf16;

// ---------------- scratch ----------------
__device__ float g_h  [TOK * DD];
__device__ float g_qkv[TOK * 3 * INNER];

__device__ __align__(128) bf16 g_h1_hi[TOK * DD],     g_h1_lo[TOK * DD];
__device__ __align__(128) bf16 g_att_hi[TOK * INNER], g_att_lo[TOK * INNER];
__device__ __align__(128) bf16 g_ff1_hi[TOK * FFN],   g_ff1_lo[TOK * FFN];
__device__ __align__(128) bf16 g_hs_hi[TOK * DD],     g_hs_lo[TOK * DD];

__device__ __align__(128) bf16 g_wqkv_hi[DD * 3 * INNER], g_wqkv_lo[DD * 3 * INNER];
__device__ __align__(128) bf16 g_wout_hi[INNER * DD],     g_wout_lo[INNER * DD];
__device__ __align__(128) bf16 g_wf1_hi[DD * FFN],        g_wf1_lo[DD * FFN];
__device__ __align__(128) bf16 g_wf2_hi[FFN * DD],        g_wf2_lo[FFN * DD];
__device__ __align__(128) bf16 g_wh_hi[(size_t)DD * VOCAB], g_wh_lo[(size_t)DD * VOCAB];

// ---------------- helpers ----------------
__device__ __forceinline__ unsigned sptr(const void* p) {
    return (unsigned)__cvta_generic_to_shared(p);
}
__device__ __forceinline__ unsigned pack_bf16x2(bf16 a, bf16 b) {
    __nv_bfloat162 p = __halves2bfloat162(a, b);
    return *(unsigned*)&p;
}
__device__ __forceinline__ void split2(float v0, float v1, unsigned& hi, unsigned& lo) {
    bf16 h0 = __float2bfloat16(v0);
    bf16 h1 = __float2bfloat16(v1);
    bf16 l0 = __float2bfloat16(v0 - __bfloat162float(h0));
    bf16 l1 = __float2bfloat16(v1 - __bfloat162float(h1));
    hi = pack_bf16x2(h0, h1);
    lo = pack_bf16x2(l0, l1);
}
__device__ __forceinline__ float block_sum256(float v) {
    __shared__ float red[8];
    const unsigned FULL = 0xffffffffu;
    #pragma unroll
    for (int o = 16; o > 0; o >>= 1) v += __shfl_down_sync(FULL, v, o);
    __syncthreads();
    if ((threadIdx.x & 31) == 0) red[threadIdx.x >> 5] = v;
    __syncthreads();
    float s = 0.f;
    #pragma unroll
    for (int i = 0; i < 8; i++) s += red[i];
    return s;
}
__device__ __forceinline__ int fetch_token(const void* xraw, int t) {
    const int* x32 = (const int*)xraw;
    bool is64 = true;
    #pragma unroll
    for (int i = 0; i < 8; i++) if (x32[2 * i + 1] != 0) is64 = false;
    return is64 ? (int)(((const long long*)xraw)[t]) : x32[t];
}

// ---------------- weight split: fp32 -> bf16 hi/lo ----------------
__global__ void split_kernel(const float4* __restrict__ s,
                             uint2* __restrict__ hi, uint2* __restrict__ lo, int n4) {
    int i = blockIdx.x * blockDim.x + threadIdx.x;
    int stride = gridDim.x * blockDim.x;
    for (; i < n4; i += stride) {
        float4 v = s[i];
        unsigned h01, l01, h23, l23;
        split2(v.x, v.y, h01, l01);
        split2(v.z, v.w, h23, l23);
        hi[i] = make_uint2(h01, h23);
        lo[i] = make_uint2(l01, l23);
    }
}

// ---------------- embed + pos + LN1 ----------------
__global__ void embed_ln_kernel(const void* __restrict__ x,
                                const float* __restrict__ emb,
                                const float* __restrict__ pos,
                                const float* __restrict__ g,
                                const float* __restrict__ b,
                                float* __restrict__ h,
                                bf16* __restrict__ o_hi, bf16* __restrict__ o_lo) {
    const int t    = blockIdx.x;
    const int tpos = t & (TT - 1);
    const int tok = fetch_token(x, t);
    const float* e = emb + (size_t)tok * DD;
    const float* p = pos + (size_t)tpos * DD;

    float local[4];
    float s = 0.f;
    #pragma unroll
    for (int i = 0; i < 4; i++) {
        int idx = threadIdx.x + i * 256;
        float v = e[idx] + p[idx];
        local[i] = v;
        h[(size_t)t * DD + idx] = v;
        s += v;
    }
    float S = block_sum256(s);
    float mu = S * (1.0f / DD);
    float s2 = 0.f;
    #pragma unroll
    for (int i = 0; i < 4; i++) { float d = local[i] - mu; s2 += d * d; }
    float V = block_sum256(s2);
    float rstd = rsqrtf(V * (1.0f / DD) + 1e-5f);
    #pragma unroll
    for (int i = 0; i < 4; i++) {
        int idx = threadIdx.x + i * 256;
        float v = (local[i] - mu) * rstd * g[idx] + b[idx];
        bf16 hv = __float2bfloat16(v);
        o_hi[(size_t)t * DD + idx] = hv;
        o_lo[(size_t)t * DD + idx] = __float2bfloat16(v - __bfloat162float(hv));
    }
}

// ---------------- LN2 ----------------
__global__ void ln_kernel(const float* __restrict__ h,
                          const float* __restrict__ g,
                          const float* __restrict__ b,
                          bf16* __restrict__ o_hi, bf16* __restrict__ o_lo) {
    const int t = blockIdx.x;
    float local[4];
    float s = 0.f;
    #pragma unroll
    for (int i = 0; i < 4; i++) {
        int idx = threadIdx.x + i * 256;
        float v = h[(size_t)t * DD + idx];
        local[i] = v;
        s += v;
    }
    float S = block_sum256(s);
    float mu = S * (1.0f / DD);
    float s2 = 0.f;
    #pragma unroll
    for (int i = 0; i < 4; i++) { float d = local[i] - mu; s2 += d * d; }
    float V = block_sum256(s2);
    float rstd = rsqrtf(V * (1.0f / DD) + 1e-5f);
    #pragma unroll
    for (int i = 0; i < 4; i++) {
        int idx = threadIdx.x + i * 256;
        float v = (local[i] - mu) * rstd * g[idx] + b[idx];
        bf16 hv = __float2bfloat16(v);
        o_hi[(size_t)t * DD + idx] = hv;
        o_lo[(size_t)t * DD + idx] = __float2bfloat16(v - __bfloat162float(hv));
    }
}

// ================= mma.sync GEMM v3.1: pre-split bf16x3, 3-stage cp.async =================
// D(MxN) = A(MxK)@B(KxN), A=Ah+Al, B=Bh+Bl (drop Al*Bl).
// CTA 128x128, BK=32, 256 thr, 8 warps (4M x 2N), warp tile 32x64.
// SMEM stage layout (bytes): A_hi[128*80] A_lo[128*80] B_hi[32*272] B_lo[32*272] = 37888.
#define LDA_S   40                  // A smem row stride in bf16 elems (80B)
#define LDB_S   136                 // B smem row stride in bf16 elems (272B)
#define A_OFF_LO 10240
#define B_OFF_HI 20480
#define B_OFF_LO 29184
#define STAGE_B  37888
#define NSTAGE   3
#define GSMEM_BYTES (NSTAGE * STAGE_B)

__device__ __forceinline__ void ldmatrix_x4(unsigned* r, unsigned addr) {
    asm volatile("ldmatrix.sync.aligned.m8n8.x4.shared.b16 {%0,%1,%2,%3}, [%4];"
                 : "=r"(r[0]), "=r"(r[1]), "=r"(r[2]), "=r"(r[3]) : "r"(addr));
}
__device__ __forceinline__ void ldmatrix_x4_trans(unsigned* r, unsigned addr) {
    asm volatile("ldmatrix.sync.aligned.m8n8.x4.trans.shared.b16 {%0,%1,%2,%3}, [%4];"
                 : "=r"(r[0]), "=r"(r[1]), "=r"(r[2]), "=r"(r[3]) : "r"(addr));
}
__device__ __forceinline__ void mma_bf16(float* c, const unsigned* a, const unsigned* b) {
    asm volatile("mma.sync.aligned.m16n8k16.row.col.f32.bf16.bf16.f32 "
                 "{%0,%1,%2,%3}, {%4,%5,%6,%7}, {%8,%9}, {%0,%1,%2,%3};"
                 : "+f"(c[0]), "+f"(c[1]), "+f"(c[2]), "+f"(c[3])
                 : "r"(a[0]), "r"(a[1]), "r"(a[2]), "r"(a[3]), "r"(b[0]), "r"(b[1]));
}
__device__ __forceinline__ void cp16(unsigned dst, const void* g) {
    asm volatile("cp.async.cg.shared.global [%0], [%1], 16;" :: "r"(dst), "l"(g));
}
__device__ __forceinline__ void cp_commit() { asm volatile("cp.async.commit_group;" ::: "memory"); }

template<int DO_BIAS, int DO_ADDC, int DO_GELU, int DO_SPLIT, int DO_F32>
__global__ __launch_bounds__(256)
void gemm_bf3(int M, int N, int K,
              const bf16* __restrict__ Ah, const bf16* __restrict__ Al,
              const bf16* __restrict__ Bh, const bf16* __restrict__ Bl,
              const float* __restrict__ Cadd, const float* __restrict__ bias,
              float* __restrict__ D, bf16* __restrict__ Dh, bf16* __restrict__ Dl) {
    extern __shared__ __align__(16) char smraw[];
    const unsigned sbase = sptr(smraw);

    const int tid  = threadIdx.x;
    const int lane = tid & 31;
    const int warp = tid >> 5;
    const int wm   = warp & 3;
    const int wn   = warp >> 2;
    const int bx = blockIdx.x;   // N tile
    const int by = blockIdx.y;   // M tile

    float acc[2][8][4];
    #pragma unroll
    for (int i = 0; i < 2; i++)
        #pragma unroll
        for (int j = 0; j < 8; j++)
            #pragma unroll
            for (int q = 0; q < 4; q++) acc[i][j][q] = 0.f;

    // ldmatrix per-lane coords (bf16 elem units)
    const int a_row = wm * 32 + (lane & 15);
    const int a_col = (lane >> 4) * 8;
    const int b_row = (lane & 15);
    const int b_col = wn * 64 + (lane >> 4) * 8;

    // cp.async per-thread assignments
    // A: 128 rows x 4 chunks (16B) per part = 512 chunks -> 2 per thread
    const int aL_r = tid >> 2;            // 0..63 (+64 for 2nd)
    const int aL_k = (tid & 3) * 8;
    // B: 32 rows x 16 chunks per part = 512 chunks -> 2 per thread
    const int bL_r = tid >> 4;            // 0..15 (+16 for 2nd)
    const int bL_k = (tid & 15) * 8;      // 0..120

    const size_t aG0 = (size_t)(by * 128 + aL_r) * K + aL_k;
    const size_t bG0 = (size_t)bL_r * N + bx * 128 + bL_k;
    const unsigned sA0 = sbase + aL_r * (LDA_S * 2) + aL_k * 2;
    const unsigned sA1 = sbase + (aL_r + 64) * (LDA_S * 2) + aL_k * 2;
    const unsigned sB0 = sbase + B_OFF_HI + bL_r * (LDB_S * 2) + bL_k * 2;
    const unsigned sB1 = sbase + B_OFF_HI + (bL_r + 16) * (LDB_S * 2) + bL_k * 2;

    const int KT = K >> 5;

    auto load_stage = [&](int st, int kt) {
        const unsigned so = st * STAGE_B;
        const int k0 = kt << 5;
        cp16(sA0 + so,            Ah + aG0 + k0);
        cp16(sA1 + so,            Ah + aG0 + 64 * (size_t)K + k0);
        cp16(sA0 + so + A_OFF_LO, Al + aG0 + k0);
        cp16(sA1 + so + A_OFF_LO, Al + aG0 + 64 * (size_t)K + k0);
        const size_t bo0 = bG0 + (size_t)k0 * N;
        const size_t bo1 = bo0 + 16 * (size_t)N;
        cp16(sB0 + so,                         Bh + bo0);
        cp16(sB1 + so,                         Bh + bo1);
        cp16(sB0 + so + (B_OFF_LO - B_OFF_HI), Bl + bo0);
        cp16(sB1 + so + (B_OFF_LO - B_OFF_HI), Bl + bo1);
        cp_commit();
    };

    load_stage(0, 0);
    load_stage(1, 1);

    int st = 0;
    for (int kt = 0; kt < KT; kt++) {
        if (kt + 1 < KT) asm volatile("cp.async.wait_group 1;" ::: "memory");
        else             asm volatile("cp.async.wait_group 0;" ::: "memory");
        __syncthreads();

        if (kt + 2 < KT) {
            int st2 = st + 2; if (st2 >= NSTAGE) st2 -= NSTAGE;
            load_stage(st2, kt + 2);
        }

        const unsigned so = sbase + st * STAGE_B;
        #pragma unroll
        for (int ks = 0; ks < 2; ks++) {
            unsigned ah[2][4], al[2][4];
            #pragma unroll
            for (int mt = 0; mt < 2; mt++) {
                unsigned arow_off = (a_row + mt * 16) * (LDA_S * 2) + (ks * 16 + a_col) * 2;
                ldmatrix_x4(ah[mt], so + arow_off);
                ldmatrix_x4(al[mt], so + A_OFF_LO + arow_off);
            }
            #pragma unroll
            for (int nh = 0; nh < 2; nh++) {
                unsigned bh[8], bl[8];
                #pragma unroll
                for (int ntp = 0; ntp < 2; ntp++) {
                    unsigned boff = (ks * 16 + b_row) * (LDB_S * 2) + (b_col + nh * 32 + ntp * 16) * 2;
                    ldmatrix_x4_trans(&bh[ntp * 4], so + B_OFF_HI + boff);
                    ldmatrix_x4_trans(&bl[ntp * 4], so + B_OFF_LO + boff);
                }
                #pragma unroll
                for (int mt = 0; mt < 2; mt++)
                    #pragma unroll
                    for (int nt = 0; nt < 4; nt++) {
                        float* a4 = acc[mt][nh * 4 + nt];
                        mma_bf16(a4, ah[mt], &bh[nt * 2]);
                        mma_bf16(a4, al[mt], &bh[nt * 2]);
                        mma_bf16(a4, ah[mt], &bl[nt * 2]);
                    }
            }
        }
        if (++st == NSTAGE) st = 0;
    }

    // ---- epilogue (round-4 mapping) ----
    const int row_base = by * 128 + wm * 32 + (lane >> 2);
    const int col_base = bx * 128 + wn * 64 + (lane & 3) * 2;
    #pragma unroll
    for (int mt = 0; mt < 2; mt++) {
        #pragma unroll
        for (int nt = 0; nt < 8; nt++) {
            int col = col_base + nt * 8;
            float2 vb;
            if (DO_BIAS) vb = *(const float2*)&bias[col];
            #pragma unroll
            for (int half = 0; half < 2; half++) {
                int row = row_base + mt * 16 + half * 8;
                float v0 = acc[mt][nt][half * 2 + 0];
                float v1 = acc[mt][nt][half * 2 + 1];
                if (DO_BIAS) { v0 += vb.x; v1 += vb.y; }
                if (DO_GELU) { v0 = v0 * normcdff(v0); v1 = v1 * normcdff(v1); }
                size_t off = (size_t)row * N + col;
                if (DO_ADDC) {
                    float2 c = *(const float2*)&Cadd[off];
                    v0 += c.x; v1 += c.y;
                }
                if (DO_F32) {
                    float2 o; o.x = v0; o.y = v1;
                    *(float2*)&D[off] = o;
                }
                if (DO_SPLIT) {
                    unsigned hp, lp;
                    split2(v0, v1, hp, lp);
                    *(unsigned*)&Dh[off] = hp;
                    *(unsigned*)&Dl[off] = lp;
                }
            }
        }
    }
}

// ---------------- flash attention (fp32 in, split out) ----------------
__global__ __launch_bounds__(64)
void flash_attn_kernel(const float* __restrict__ qkv,
                       bf16* __restrict__ o_hi, bf16* __restrict__ o_lo) {
    const int tid = threadIdx.x;
    const int qt = blockIdx.x;
    const int hh = blockIdx.y;
    const int b  = blockIdx.z;

    __shared__ float k_sm[64 * 64];
    __shared__ float v_sm[64 * 64];

    const int q_row = qt * 64 + tid;
    const float* qp = qkv + ((size_t)(b * TT + q_row)) * (3 * INNER) + hh * HDIM;

    float q[64], acc[64];
    #pragma unroll
    for (int d = 0; d < 64; d++) { q[d] = qp[d] * 0.125f; acc[d] = 0.f; }
    float m = -3.0e38f, l = 0.f;

    for (int kt = 0; kt <= qt; kt++) {
        const float* kb = qkv + ((size_t)(b * TT + kt * 64)) * (3 * INNER) + INNER + hh * HDIM;
        const float* vb = kb + INNER;
        __syncthreads();
        for (int r = 0; r < 64; r++) {
            k_sm[r * 64 + tid] = kb[(size_t)r * (3 * INNER) + tid];
            v_sm[r * 64 + tid] = vb[(size_t)r * (3 * INNER) + tid];
        }
        __syncthreads();

        const int valid = q_row - kt * 64;
        #pragma unroll
        for (int c = 0; c < 2; c++) {
            float s[32];
            float mt = -3.0e38f;
            for (int j = 0; j < 32; j++) {
                const int jj = c * 32 + j;
                float sv;
                if (jj <= valid) {
                    sv = 0.f;
                    #pragma unroll
                    for (int d = 0; d < 64; d++) sv += q[d] * k_sm[jj * 64 + d];
                } else {
                    sv = -3.0e38f;
                }
                s[j] = sv;
                mt = fmaxf(mt, sv);
            }
            if (mt > m) {
                float corr = expf(m - mt);
                l *= corr;
                #pragma unroll
                for (int d = 0; d < 64; d++) acc[d] *= corr;
                m = mt;
            }
            for (int j = 0; j < 32; j++) {
                float p = expf(s[j] - m);
                l += p;
                const int jj = c * 32 + j;
                #pragma unroll
                for (int d = 0; d < 64; d++) acc[d] += p * v_sm[jj * 64 + d];
            }
        }
    }

    const float inv = 1.0f / l;
    size_t base = ((size_t)(b * TT + q_row)) * INNER + hh * HDIM;
    #pragma unroll
    for (int d = 0; d < 64; d++) {
        float v = acc[d] * inv;
        bf16 hv = __float2bfloat16(v);
        o_hi[base + d] = hv;
        o_lo[base + d] = __float2bfloat16(v - __bfloat162float(hv));
    }
}

// ---------------- launch ----------------
extern "C" void kernel_launch(void* const* d_in, const int* in_sizes, int n_in,
                              void* d_out, int out_size) {
    const void*  x      = d_in[0];
    const float* emb    = (const float*)d_in[1];
    const float* pos    = (const float*)d_in[2];
    const float* w_qkv  = (const float*)d_in[3];
    const float* w_out  = (const float*)d_in[4];
    const float* ln1_g  = (const float*)d_in[5];
    const float* ln1_b  = (const float*)d_in[6];
    const float* ln2_g  = (const float*)d_in[7];
    const float* ln2_b  = (const float*)d_in[8];
    const float* w_ffn1 = (const float*)d_in[9];
    const float* b_ffn1 = (const float*)d_in[10];
    const float* w_ffn2 = (const float*)d_in[11];
    const float* b_ffn2 = (const float*)d_in[12];
    const float* w_head = (const float*)d_in[13];
    const float* b_head = (const float*)d_in[14];
    float* out = (float*)d_out;

    float *h, *qkv;
    bf16 *h1h, *h1l, *atth, *attl, *ff1h, *ff1l, *hsh, *hsl;
    bf16 *wqh, *wql, *woh, *wol, *w1h, *w1l, *w2h, *w2l, *whh, *whl;
    cudaGetSymbolAddress((void**)&h,    g_h);
    cudaGetSymbolAddress((void**)&qkv,  g_qkv);
    cudaGetSymbolAddress((void**)&h1h,  g_h1_hi);   cudaGetSymbolAddress((void**)&h1l,  g_h1_lo);
    cudaGetSymbolAddress((void**)&atth, g_att_hi);  cudaGetSymbolAddress((void**)&attl, g_att_lo);
    cudaGetSymbolAddress((void**)&ff1h, g_ff1_hi);  cudaGetSymbolAddress((void**)&ff1l, g_ff1_lo);
    cudaGetSymbolAddress((void**)&hsh,  g_hs_hi);   cudaGetSymbolAddress((void**)&hsl,  g_hs_lo);
    cudaGetSymbolAddress((void**)&wqh,  g_wqkv_hi); cudaGetSymbolAddress((void**)&wql,  g_wqkv_lo);
    cudaGetSymbolAddress((void**)&woh,  g_wout_hi); cudaGetSymbolAddress((void**)&wol,  g_wout_lo);
    cudaGetSymbolAddress((void**)&w1h,  g_wf1_hi);  cudaGetSymbolAddress((void**)&w1l,  g_wf1_lo);
    cudaGetSymbolAddress((void**)&w2h,  g_wf2_hi);  cudaGetSymbolAddress((void**)&w2l,  g_wf2_lo);
    cudaGetSymbolAddress((void**)&whh,  g_wh_hi);   cudaGetSymbolAddress((void**)&whl,  g_wh_lo);

    cudaFuncSetAttribute(gemm_bf3<0,0,0,0,1>, cudaFuncAttributeMaxDynamicSharedMemorySize, GSMEM_BYTES);
    cudaFuncSetAttribute(gemm_bf3<0,1,0,0,1>, cudaFuncAttributeMaxDynamicSharedMemorySize, GSMEM_BYTES);
    cudaFuncSetAttribute(gemm_bf3<1,0,1,1,0>, cudaFuncAttributeMaxDynamicSharedMemorySize, GSMEM_BYTES);
    cudaFuncSetAttribute(gemm_bf3<1,1,0,1,0>, cudaFuncAttributeMaxDynamicSharedMemorySize, GSMEM_BYTES);
    cudaFuncSetAttribute(gemm_bf3<1,0,0,0,1>, cudaFuncAttributeMaxDynamicSharedMemorySize, GSMEM_BYTES);

    // 0. split weights -> bf16 hi/lo (layout preserved)
    split_kernel<<<1024, 256>>>((const float4*)w_qkv,  (uint2*)wqh, (uint2*)wql, DD * 3 * INNER / 4);
    split_kernel<<<1024, 256>>>((const float4*)w_out,  (uint2*)woh, (uint2*)wol, INNER * DD / 4);
    split_kernel<<<1024, 256>>>((const float4*)w_ffn1, (uint2*)w1h, (uint2*)w1l, DD * FFN / 4);
    split_kernel<<<1024, 256>>>((const float4*)w_ffn2, (uint2*)w2h, (uint2*)w2l, FFN * DD / 4);
    split_kernel<<<2048, 256>>>((const float4*)w_head, (uint2*)whh, (uint2*)whl, DD * VOCAB / 4);

    // 1. embed + pos + ln1 -> h fp32, h1 split
    embed_ln_kernel<<<TOK, 256>>>(x, emb, pos, ln1_g, ln1_b, h, h1h, h1l);

    // 2. qkv = h1 @ w_qkv (fp32 out)
    gemm_bf3<0,0,0,0,1><<<dim3(3 * INNER / 128, TOK / 128), 256, GSMEM_BYTES>>>(
        TOK, 3 * INNER, DD, h1h, h1l, wqh, wql, nullptr, nullptr, qkv, nullptr, nullptr);

    // 3. flash attention -> att split
    flash_attn_kernel<<<dim3(TT / 64, HH, BATCH), 64>>>(qkv, atth, attl);

    // 4. h = h + att @ w_out (fp32, in place)
    gemm_bf3<0,1,0,0,1><<<dim3(DD / 128, TOK / 128), 256, GSMEM_BYTES>>>(
        TOK, DD, INNER, atth, attl, woh, wol, h, nullptr, h, nullptr, nullptr);

    // 5. h2 = ln2(h) -> split
    ln_kernel<<<TOK, 256>>>(h, ln2_g, ln2_b, h1h, h1l);

    // 6. ff1 = gelu(h2 @ w_ffn1 + b1) -> split
    gemm_bf3<1,0,1,1,0><<<dim3(FFN / 128, TOK / 128), 256, GSMEM_BYTES>>>(
        TOK, FFN, DD, h1h, h1l, w1h, w1l, nullptr, b_ffn1, nullptr, ff1h, ff1l);

    // 7. h' = h + ff1 @ w_ffn2 + b2 -> split (feeds head)
    gemm_bf3<1,1,0,1,0><<<dim3(DD / 128, TOK / 128), 256, GSMEM_BYTES>>>(
        TOK, DD, FFN, ff1h, ff1l, w2h, w2l, h, b_ffn2, nullptr, hsh, hsl);

    // 8. logits = h' @ w_head + b_head (fp32 out)
    gemm_bf3<1,0,0,0,1><<<dim3(VOCAB / 128, TOK / 128), 256, GSMEM_BYTES>>>(
        TOK, VOCAB, DD, hsh, hsl, whh, whl, nullptr, b_head, out, nullptr, nullptr);
}

// round 13
// speedup vs baseline: 1.1389x; 1.1141x over previous
#include <cuda_runtime.h>
#include <cuda_bf16.h>
#include <math.h>
#include <stdint.h>

#define BATCH 2
#define TT    2048
#define TOK   (BATCH * TT)      // 4096
#define DD    1024
#define HH    16
#define HDIM  64
#define INNER (HH * HDIM)       // 1024
#define VOCAB 32000
#define FFN   (4 * DD)          // 4096

typedef __nv_bfloat16 bf16;

// ---------------- scratch ----------------
__device__ float g_h  [TOK * DD];
__device__ float g_qkv[TOK * 3 * INNER];

__device__ __align__(128) bf16 g_h1_hi[TOK * DD],     g_h1_lo[TOK * DD];
__device__ __align__(128) bf16 g_att_hi[TOK * INNER], g_att_lo[TOK * INNER];
__device__ __align__(128) bf16 g_ff1_hi[TOK * FFN],   g_ff1_lo[TOK * FFN];
__device__ __align__(128) bf16 g_hs_hi[TOK * DD],     g_hs_lo[TOK * DD];

__device__ __align__(128) bf16 g_wqkv_hi[DD * 3 * INNER], g_wqkv_lo[DD * 3 * INNER];
__device__ __align__(128) bf16 g_wout_hi[INNER * DD],     g_wout_lo[INNER * DD];
__device__ __align__(128) bf16 g_wf1_hi[DD * FFN],        g_wf1_lo[DD * FFN];
__device__ __align__(128) bf16 g_wf2_hi[FFN * DD],        g_wf2_lo[FFN * DD];
__device__ __align__(128) bf16 g_wh_hi[(size_t)DD * VOCAB], g_wh_lo[(size_t)DD * VOCAB];

// ---------------- helpers ----------------
__device__ __forceinline__ unsigned sptr(const void* p) {
    return (unsigned)__cvta_generic_to_shared(p);
}
__device__ __forceinline__ unsigned pack_bf16x2(bf16 a, bf16 b) {
    __nv_bfloat162 p = __halves2bfloat162(a, b);
    return *(unsigned*)&p;
}
__device__ __forceinline__ void split2(float v0, float v1, unsigned& hi, unsigned& lo) {
    bf16 h0 = __float2bfloat16(v0);
    bf16 h1 = __float2bfloat16(v1);
    bf16 l0 = __float2bfloat16(v0 - __bfloat162float(h0));
    bf16 l1 = __float2bfloat16(v1 - __bfloat162float(h1));
    hi = pack_bf16x2(h0, h1);
    lo = pack_bf16x2(l0, l1);
}
__device__ __forceinline__ float block_sum256(float v) {
    __shared__ float red[8];
    const unsigned FULL = 0xffffffffu;
    #pragma unroll
    for (int o = 16; o > 0; o >>= 1) v += __shfl_down_sync(FULL, v, o);
    __syncthreads();
    if ((threadIdx.x & 31) == 0) red[threadIdx.x >> 5] = v;
    __syncthreads();
    float s = 0.f;
    #pragma unroll
    for (int i = 0; i < 8; i++) s += red[i];
    return s;
}
__device__ __forceinline__ int fetch_token(const void* xraw, int t) {
    const int* x32 = (const int*)xraw;
    bool is64 = true;
    #pragma unroll
    for (int i = 0; i < 8; i++) if (x32[2 * i + 1] != 0) is64 = false;
    return is64 ? (int)(((const long long*)xraw)[t]) : x32[t];
}

// ---------------- fused weight split: all 5 weights, one launch ----------------
#define N4_QKV  (DD * 3 * INNER / 4)
#define N4_OUT  (INNER * DD / 4)
#define N4_FF1  (DD * FFN / 4)
#define N4_FF2  (FFN * DD / 4)
#define N4_HEAD (DD * VOCAB / 4)

__global__ void split_all_kernel(
    const float4* __restrict__ s0, uint2* __restrict__ h0, uint2* __restrict__ l0,
    const float4* __restrict__ s1, uint2* __restrict__ h1, uint2* __restrict__ l1,
    const float4* __restrict__ s2, uint2* __restrict__ h2, uint2* __restrict__ l2,
    const float4* __restrict__ s3, uint2* __restrict__ h3, uint2* __restrict__ l3,
    const float4* __restrict__ s4, uint2* __restrict__ h4, uint2* __restrict__ l4) {
    const long long total = (long long)N4_QKV + N4_OUT + N4_FF1 + N4_FF2 + N4_HEAD;
    for (long long i = (long long)blockIdx.x * blockDim.x + threadIdx.x; i < total;
         i += (long long)gridDim.x * blockDim.x) {
        const float4* s; uint2 *hh, *ll;
        long long j = i;
        if (j < N4_QKV)              { s = s0; hh = h0; ll = l0; }
        else if ((j -= N4_QKV) < N4_OUT) { s = s1; hh = h1; ll = l1; }
        else if ((j -= N4_OUT) < N4_FF1) { s = s2; hh = h2; ll = l2; }
        else if ((j -= N4_FF1) < N4_FF2) { s = s3; hh = h3; ll = l3; }
        else { j -= N4_FF2;            s = s4; hh = h4; ll = l4; }
        float4 v = s[j];
        unsigned a, b, c, d;
        split2(v.x, v.y, a, b);
        split2(v.z, v.w, c, d);
        hh[j] = make_uint2(a, c);
        ll[j] = make_uint2(b, d);
    }
}

// ---------------- embed + pos + LN1 ----------------
__global__ void embed_ln_kernel(const void* __restrict__ x,
                                const float* __restrict__ emb,
                                const float* __restrict__ pos,
                                const float* __restrict__ g,
                                const float* __restrict__ b,
                                float* __restrict__ h,
                                bf16* __restrict__ o_hi, bf16* __restrict__ o_lo) {
    const int t    = blockIdx.x;
    const int tpos = t & (TT - 1);
    const int tok = fetch_token(x, t);
    const float* e = emb + (size_t)tok * DD;
    const float* p = pos + (size_t)tpos * DD;

    float local[4];
    float s = 0.f;
    #pragma unroll
    for (int i = 0; i < 4; i++) {
        int idx = threadIdx.x + i * 256;
        float v = e[idx] + p[idx];
        local[i] = v;
        h[(size_t)t * DD + idx] = v;
        s += v;
    }
    float S = block_sum256(s);
    float mu = S * (1.0f / DD);
    float s2 = 0.f;
    #pragma unroll
    for (int i = 0; i < 4; i++) { float d = local[i] - mu; s2 += d * d; }
    float V = block_sum256(s2);
    float rstd = rsqrtf(V * (1.0f / DD) + 1e-5f);
    #pragma unroll
    for (int i = 0; i < 4; i++) {
        int idx = threadIdx.x + i * 256;
        float v = (local[i] - mu) * rstd * g[idx] + b[idx];
        bf16 hv = __float2bfloat16(v);
        o_hi[(size_t)t * DD + idx] = hv;
        o_lo[(size_t)t * DD + idx] = __float2bfloat16(v - __bfloat162float(hv));
    }
}

// ---------------- LN2 ----------------
__global__ void ln_kernel(const float* __restrict__ h,
                          const float* __restrict__ g,
                          const float* __restrict__ b,
                          bf16* __restrict__ o_hi, bf16* __restrict__ o_lo) {
    const int t = blockIdx.x;
    float local[4];
    float s = 0.f;
    #pragma unroll
    for (int i = 0; i < 4; i++) {
        int idx = threadIdx.x + i * 256;
        float v = h[(size_t)t * DD + idx];
        local[i] = v;
        s += v;
    }
    float S = block_sum256(s);
    float mu = S * (1.0f / DD);
    float s2 = 0.f;
    #pragma unroll
    for (int i = 0; i < 4; i++) { float d = local[i] - mu; s2 += d * d; }
    float V = block_sum256(s2);
    float rstd = rsqrtf(V * (1.0f / DD) + 1e-5f);
    #pragma unroll
    for (int i = 0; i < 4; i++) {
        int idx = threadIdx.x + i * 256;
        float v = (local[i] - mu) * rstd * g[idx] + b[idx];
        bf16 hv = __float2bfloat16(v);
        o_hi[(size_t)t * DD + idx] = hv;
        o_lo[(size_t)t * DD + idx] = __float2bfloat16(v - __bfloat162float(hv));
    }
}

// ================= mma.sync GEMM v4: pre-split bf16x3, 2-stage cp.async, 2 CTA/SM =================
// D(MxN) = A(MxK)@B(KxN), A=Ah+Al, B=Bh+Bl (drop Al*Bl).
// CTA 128x128, BK=32, 256 thr, 8 warps (4M x 2N), warp tile 32x64.
// Grid: blockIdx.x = M tile (fast) -> B tiles shared in L2 across the 32 M-CTAs.
#define LDA_S   40
#define LDB_S   136
#define A_OFF_LO 10240
#define B_OFF_HI 20480
#define B_OFF_LO 29184
#define STAGE_B  37888
#define GSMEM_BYTES (2 * STAGE_B)

__device__ __forceinline__ void ldmatrix_x4(unsigned* r, unsigned addr) {
    asm volatile("ldmatrix.sync.aligned.m8n8.x4.shared.b16 {%0,%1,%2,%3}, [%4];"
                 : "=r"(r[0]), "=r"(r[1]), "=r"(r[2]), "=r"(r[3]) : "r"(addr));
}
__device__ __forceinline__ void ldmatrix_x4_trans(unsigned* r, unsigned addr) {
    asm volatile("ldmatrix.sync.aligned.m8n8.x4.trans.shared.b16 {%0,%1,%2,%3}, [%4];"
                 : "=r"(r[0]), "=r"(r[1]), "=r"(r[2]), "=r"(r[3]) : "r"(addr));
}
__device__ __forceinline__ void mma_bf16(float* c, const unsigned* a, const unsigned* b) {
    asm volatile("mma.sync.aligned.m16n8k16.row.col.f32.bf16.bf16.f32 "
                 "{%0,%1,%2,%3}, {%4,%5,%6,%7}, {%8,%9}, {%0,%1,%2,%3};"
                 : "+f"(c[0]), "+f"(c[1]), "+f"(c[2]), "+f"(c[3])
                 : "r"(a[0]), "r"(a[1]), "r"(a[2]), "r"(a[3]), "r"(b[0]), "r"(b[1]));
}
__device__ __forceinline__ void cp16(unsigned dst, const void* g) {
    asm volatile("cp.async.cg.shared.global [%0], [%1], 16;" :: "r"(dst), "l"(g));
}
__device__ __forceinline__ void cp_commit() { asm volatile("cp.async.commit_group;" ::: "memory"); }

template<int DO_BIAS, int DO_ADDC, int DO_GELU, int DO_SPLIT, int DO_F32>
__global__ __launch_bounds__(256, 2)
void gemm_bf3(int M, int N, int K,
              const bf16* __restrict__ Ah, const bf16* __restrict__ Al,
              const bf16* __restrict__ Bh, const bf16* __restrict__ Bl,
              const float* __restrict__ Cadd, const float* __restrict__ bias,
              float* __restrict__ D, bf16* __restrict__ Dh, bf16* __restrict__ Dl) {
    extern __shared__ __align__(16) char smraw[];
    const unsigned sbase = sptr(smraw);

    const int tid  = threadIdx.x;
    const int lane = tid & 31;
    const int warp = tid >> 5;
    const int wm   = warp & 3;
    const int wn   = warp >> 2;
    const int bm = blockIdx.x;   // M tile (fast dim)
    const int bn = blockIdx.y;   // N tile

    float acc[2][8][4];
    #pragma unroll
    for (int i = 0; i < 2; i++)
        #pragma unroll
        for (int j = 0; j < 8; j++)
            #pragma unroll
            for (int q = 0; q < 4; q++) acc[i][j][q] = 0.f;

    // ldmatrix per-lane coords (bf16 elem units)
    const int a_row = wm * 32 + (lane & 15);
    const int a_col = (lane >> 4) * 8;
    const int b_row = (lane & 15);
    const int b_col = wn * 64 + (lane >> 4) * 8;

    // cp.async per-thread assignments
    const int aL_r = tid >> 2;            // A rows 0..63 (+64)
    const int aL_k = (tid & 3) * 8;
    const int bL_r = tid >> 4;            // B rows 0..15 (+16)
    const int bL_k = (tid & 15) * 8;      // cols 0..120

    const size_t aG0 = (size_t)(bm * 128 + aL_r) * K + aL_k;
    const size_t bG0 = (size_t)bL_r * N + bn * 128 + bL_k;
    const unsigned sA0 = sbase + aL_r * (LDA_S * 2) + aL_k * 2;
    const unsigned sA1 = sbase + (aL_r + 64) * (LDA_S * 2) + aL_k * 2;
    const unsigned sB0 = sbase + B_OFF_HI + bL_r * (LDB_S * 2) + bL_k * 2;
    const unsigned sB1 = sbase + B_OFF_HI + (bL_r + 16) * (LDB_S * 2) + bL_k * 2;

    const int KT = K >> 5;

    auto load_stage = [&](int st, int kt) {
        const unsigned so = st * STAGE_B;
        const int k0 = kt << 5;
        cp16(sA0 + so,            Ah + aG0 + k0);
        cp16(sA1 + so,            Ah + aG0 + 64 * (size_t)K + k0);
        cp16(sA0 + so + A_OFF_LO, Al + aG0 + k0);
        cp16(sA1 + so + A_OFF_LO, Al + aG0 + 64 * (size_t)K + k0);
        const size_t bo0 = bG0 + (size_t)k0 * N;
        const size_t bo1 = bo0 + 16 * (size_t)N;
        cp16(sB0 + so,                         Bh + bo0);
        cp16(sB1 + so,                         Bh + bo1);
        cp16(sB0 + so + (B_OFF_LO - B_OFF_HI), Bl + bo0);
        cp16(sB1 + so + (B_OFF_LO - B_OFF_HI), Bl + bo1);
        cp_commit();
    };

    load_stage(0, 0);

    int st = 0;
    for (int kt = 0; kt < KT; kt++) {
        if (kt + 1 < KT) {
            load_stage(st ^ 1, kt + 1);
            asm volatile("cp.async.wait_group 1;" ::: "memory");
        } else {
            asm volatile("cp.async.wait_group 0;" ::: "memory");
        }
        __syncthreads();                 // tile kt visible

        const unsigned so = sbase + st * STAGE_B;
        #pragma unroll
        for (int ks = 0; ks < 2; ks++) {
            unsigned ah[2][4], al[2][4];
            #pragma unroll
            for (int mt = 0; mt < 2; mt++) {
                unsigned arow_off = (a_row + mt * 16) * (LDA_S * 2) + (ks * 16 + a_col) * 2;
                ldmatrix_x4(ah[mt], so + arow_off);
                ldmatrix_x4(al[mt], so + A_OFF_LO + arow_off);
            }
            #pragma unroll
            for (int nh = 0; nh < 2; nh++) {
                unsigned bh[8], bl[8];
                #pragma unroll
                for (int ntp = 0; ntp < 2; ntp++) {
                    unsigned boff = (ks * 16 + b_row) * (LDB_S * 2) + (b_col + nh * 32 + ntp * 16) * 2;
                    ldmatrix_x4_trans(&bh[ntp * 4], so + B_OFF_HI + boff);
                    ldmatrix_x4_trans(&bl[ntp * 4], so + B_OFF_LO + boff);
                }
                #pragma unroll
                for (int mt = 0; mt < 2; mt++)
                    #pragma unroll
                    for (int nt = 0; nt < 4; nt++) {
                        float* a4 = acc[mt][nh * 4 + nt];
                        mma_bf16(a4, ah[mt], &bh[nt * 2]);
                        mma_bf16(a4, al[mt], &bh[nt * 2]);
                        mma_bf16(a4, ah[mt], &bl[nt * 2]);
                    }
            }
        }
        __syncthreads();                 // stage st free for overwrite
        st ^= 1;
    }

    // ---- epilogue ----
    const int row_base = bm * 128 + wm * 32 + (lane >> 2);
    const int col_base = bn * 128 + wn * 64 + (lane & 3) * 2;
    #pragma unroll
    for (int mt = 0; mt < 2; mt++) {
        #pragma unroll
        for (int nt = 0; nt < 8; nt++) {
            int col = col_base + nt * 8;
            float2 vb;
            if (DO_BIAS) vb = *(const float2*)&bias[col];
            #pragma unroll
            for (int half = 0; half < 2; half++) {
                int row = row_base + mt * 16 + half * 8;
                float v0 = acc[mt][nt][half * 2 + 0];
                float v1 = acc[mt][nt][half * 2 + 1];
                if (DO_BIAS) { v0 += vb.x; v1 += vb.y; }
                if (DO_GELU) { v0 = v0 * normcdff(v0); v1 = v1 * normcdff(v1); }
                size_t off = (size_t)row * N + col;
                if (DO_ADDC) {
                    float2 c = *(const float2*)&Cadd[off];
                    v0 += c.x; v1 += c.y;
                }
                if (DO_F32) {
                    float2 o; o.x = v0; o.y = v1;
                    *(float2*)&D[off] = o;
                }
                if (DO_SPLIT) {
                    unsigned hp, lp;
                    split2(v0, v1, hp, lp);
                    *(unsigned*)&Dh[off] = hp;
                    *(unsigned*)&Dl[off] = lp;
                }
            }
        }
    }
}

// ---------------- flash attention (fp32 in, split out) ----------------
__global__ __launch_bounds__(64)
void flash_attn_kernel(const float* __restrict__ qkv,
                       bf16* __restrict__ o_hi, bf16* __restrict__ o_lo) {
    const int tid = threadIdx.x;
    const int qt = blockIdx.x;
    const int hh = blockIdx.y;
    const int b  = blockIdx.z;

    __shared__ float k_sm[64 * 64];
    __shared__ float v_sm[64 * 64];

    const int q_row = qt * 64 + tid;
    const float* qp = qkv + ((size_t)(b * TT + q_row)) * (3 * INNER) + hh * HDIM;

    float q[64], acc[64];
    #pragma unroll
    for (int d = 0; d < 64; d++) { q[d] = qp[d] * 0.125f; acc[d] = 0.f; }
    float m = -3.0e38f, l = 0.f;

    for (int kt = 0; kt <= qt; kt++) {
        const float* kb = qkv + ((size_t)(b * TT + kt * 64)) * (3 * INNER) + INNER + hh * HDIM;
        const float* vb = kb + INNER;
        __syncthreads();
        for (int r = 0; r < 64; r++) {
            k_sm[r * 64 + tid] = kb[(size_t)r * (3 * INNER) + tid];
            v_sm[r * 64 + tid] = vb[(size_t)r * (3 * INNER) + tid];
        }
        __syncthreads();

        const int valid = q_row - kt * 64;
        #pragma unroll
        for (int c = 0; c < 2; c++) {
            float s[32];
            float mt = -3.0e38f;
            for (int j = 0; j < 32; j++) {
                const int jj = c * 32 + j;
                float sv;
                if (jj <= valid) {
                    sv = 0.f;
                    #pragma unroll
                    for (int d = 0; d < 64; d++) sv += q[d] * k_sm[jj * 64 + d];
                } else {
                    sv = -3.0e38f;
                }
                s[j] = sv;
                mt = fmaxf(mt, sv);
            }
            if (mt > m) {
                float corr = expf(m - mt);
                l *= corr;
                #pragma unroll
                for (int d = 0; d < 64; d++) acc[d] *= corr;
                m = mt;
            }
            for (int j = 0; j < 32; j++) {
                float p = expf(s[j] - m);
                l += p;
                const int jj = c * 32 + j;
                #pragma unroll
                for (int d = 0; d < 64; d++) acc[d] += p * v_sm[jj * 64 + d];
            }
        }
    }

    const float inv = 1.0f / l;
    size_t base = ((size_t)(b * TT + q_row)) * INNER + hh * HDIM;
    #pragma unroll
    for (int d = 0; d < 64; d++) {
        float v = acc[d] * inv;
        bf16 hv = __float2bfloat16(v);
        o_hi[base + d] = hv;
        o_lo[base + d] = __float2bfloat16(v - __bfloat162float(hv));
    }
}

// ---------------- launch ----------------
extern "C" void kernel_launch(void* const* d_in, const int* in_sizes, int n_in,
                              void* d_out, int out_size) {
    const void*  x      = d_in[0];
    const float* emb    = (const float*)d_in[1];
    const float* pos    = (const float*)d_in[2];
    const float* w_qkv  = (const float*)d_in[3];
    const float* w_out  = (const float*)d_in[4];
    const float* ln1_g  = (const float*)d_in[5];
    const float* ln1_b  = (const float*)d_in[6];
    const float* ln2_g  = (const float*)d_in[7];
    const float* ln2_b  = (const float*)d_in[8];
    const float* w_ffn1 = (const float*)d_in[9];
    const float* b_ffn1 = (const float*)d_in[10];
    const float* w_ffn2 = (const float*)d_in[11];
    const float* b_ffn2 = (const float*)d_in[12];
    const float* w_head = (const float*)d_in[13];
    const float* b_head = (const float*)d_in[14];
    float* out = (float*)d_out;

    float *h, *qkv;
    bf16 *h1h, *h1l, *atth, *attl, *ff1h, *ff1l, *hsh, *hsl;
    bf16 *wqh, *wql, *woh, *wol, *w1h, *w1l, *w2h, *w2l, *whh, *whl;
    cudaGetSymbolAddress((void**)&h,    g_h);
    cudaGetSymbolAddress((void**)&qkv,  g_qkv);
    cudaGetSymbolAddress((void**)&h1h,  g_h1_hi);   cudaGetSymbolAddress((void**)&h1l,  g_h1_lo);
    cudaGetSymbolAddress((void**)&atth, g_att_hi);  cudaGetSymbolAddress((void**)&attl, g_att_lo);
    cudaGetSymbolAddress((void**)&ff1h, g_ff1_hi);  cudaGetSymbolAddress((void**)&ff1l, g_ff1_lo);
    cudaGetSymbolAddress((void**)&hsh,  g_hs_hi);   cudaGetSymbolAddress((void**)&hsl,  g_hs_lo);
    cudaGetSymbolAddress((void**)&wqh,  g_wqkv_hi); cudaGetSymbolAddress((void**)&wql,  g_wqkv_lo);
    cudaGetSymbolAddress((void**)&woh,  g_wout_hi); cudaGetSymbolAddress((void**)&wol,  g_wout_lo);
    cudaGetSymbolAddress((void**)&w1h,  g_wf1_hi);  cudaGetSymbolAddress((void**)&w1l,  g_wf1_lo);
    cudaGetSymbolAddress((void**)&w2h,  g_wf2_hi);  cudaGetSymbolAddress((void**)&w2l,  g_wf2_lo);
    cudaGetSymbolAddress((void**)&whh,  g_wh_hi);   cudaGetSymbolAddress((void**)&whl,  g_wh_lo);

    cudaFuncSetAttribute(gemm_bf3<0,0,0,0,1>, cudaFuncAttributeMaxDynamicSharedMemorySize, GSMEM_BYTES);
    cudaFuncSetAttribute(gemm_bf3<0,1,0,0,1>, cudaFuncAttributeMaxDynamicSharedMemorySize, GSMEM_BYTES);
    cudaFuncSetAttribute(gemm_bf3<1,0,1,1,0>, cudaFuncAttributeMaxDynamicSharedMemorySize, GSMEM_BYTES);
    cudaFuncSetAttribute(gemm_bf3<1,1,0,1,0>, cudaFuncAttributeMaxDynamicSharedMemorySize, GSMEM_BYTES);
    cudaFuncSetAttribute(gemm_bf3<1,0,0,0,1>, cudaFuncAttributeMaxDynamicSharedMemorySize, GSMEM_BYTES);

    // 0. fused weight split (one launch)
    split_all_kernel<<<2048, 256>>>(
        (const float4*)w_qkv,  (uint2*)wqh, (uint2*)wql,
        (const float4*)w_out,  (uint2*)woh, (uint2*)wol,
        (const float4*)w_ffn1, (uint2*)w1h, (uint2*)w1l,
        (const float4*)w_ffn2, (uint2*)w2h, (uint2*)w2l,
        (const float4*)w_head, (uint2*)whh, (uint2*)whl);

    // 1. embed + pos + ln1 -> h fp32, h1 split
    embed_ln_kernel<<<TOK, 256>>>(x, emb, pos, ln1_g, ln1_b, h, h1h, h1l);

    // 2. qkv = h1 @ w_qkv (fp32 out)       grid (M, N)
    gemm_bf3<0,0,0,0,1><<<dim3(TOK / 128, 3 * INNER / 128), 256, GSMEM_BYTES>>>(
        TOK, 3 * INNER, DD, h1h, h1l, wqh, wql, nullptr, nullptr, qkv, nullptr, nullptr);

    // 3. flash attention -> att split
    flash_attn_kernel<<<dim3(TT / 64, HH, BATCH), 64>>>(qkv, atth, attl);

    // 4. h = h + att @ w_out (fp32, in place)
    gemm_bf3<0,1,0,0,1><<<dim3(TOK / 128, DD / 128), 256, GSMEM_BYTES>>>(
        TOK, DD, INNER, atth, attl, woh, wol, h, nullptr, h, nullptr, nullptr);

    // 5. h2 = ln2(h) -> split
    ln_kernel<<<TOK, 256>>>(h, ln2_g, ln2_b, h1h, h1l);

    // 6. ff1 = gelu(h2 @ w_ffn1 + b1) -> split
    gemm_bf3<1,0,1,1,0><<<dim3(TOK / 128, FFN / 128), 256, GSMEM_BYTES>>>(
        TOK, FFN, DD, h1h, h1l, w1h, w1l, nullptr, b_ffn1, nullptr, ff1h, ff1l);

    // 7. h' = h + ff1 @ w_ffn2 + b2 -> split (feeds head)
    gemm_bf3<1,1,0,1,0><<<dim3(TOK / 128, DD / 128), 256, GSMEM_BYTES>>>(
        TOK, DD, FFN, ff1h, ff1l, w2h, w2l, h, b_ffn2, nullptr, hsh, hsl);

    // 8. logits = h' @ w_head + b_head (fp32 out)
    gemm_bf3<1,0,0,0,1><<<dim3(TOK / 128, VOCAB / 128), 256, GSMEM_BYTES>>>(
        TOK, VOCAB, DD, hsh, hsl, whh, whl, nullptr, b_head, out, nullptr, nullptr);
}